// round 2
// baseline (speedup 1.0000x reference)
#include <cuda_runtime.h>
#include <math.h>
#include <stdint.h>

#define NS 4
#define MB 2
#define BLK 1024
#define EMBED 2048
#define ROWS 16384
#define RMS_EPS 1.1920928955078125e-07f
#define INV_SCALE (1.0f/32.0f)

// Scratch (device globals: allocation-free per harness rules).
// __align__(256): these are accessed through float4* — a bare float array only
// guarantees 4B alignment and a misaligned LD.E.128 traps (err715).
__device__ __align__(256) float g_xread[(size_t)ROWS * EMBED];   // (B, 2048) fp32, m-major
__device__ __align__(256) float g_mod[(size_t)ROWS * EMBED];     // (B, 2048) GEMM output
__device__ __align__(256) float g_coef[(size_t)ROWS * 24];       // per-row: wo[8], sm[16]

// ---------------------------------------------------------------------------
// Kernel 1: RMS stats + dynamic mixing coefficients + x_read
// ---------------------------------------------------------------------------
__global__ __launch_bounds__(256) void prep_kernel(
    const float* __restrict__ x,
    const float* __restrict__ wo_s, const float* __restrict__ ds_wo, const float* __restrict__ W_wo,
    const float* __restrict__ ri_s, const float* __restrict__ ds_ri, const float* __restrict__ W_ri,
    const float* __restrict__ sm_s, const float* __restrict__ ds_sm, const float* __restrict__ W_sm)
{
    const int b    = blockIdx.x;
    const int t    = threadIdx.x;
    const int lane = t & 31;
    const int warp = t >> 5;

    const float4* xb = (const float4*)(x + (size_t)b * 4096);

    // Load this thread's slice of all 4 streams (float4 per stream)
    float4 v[NS];
#pragma unroll
    for (int n = 0; n < NS; n++) v[n] = xb[n * 256 + t];

    // sum of squares per stream
    float ss[NS];
#pragma unroll
    for (int n = 0; n < NS; n++)
        ss[n] = v[n].x*v[n].x + v[n].y*v[n].y + v[n].z*v[n].z + v[n].w*v[n].w;

    // 32 dot-product partials: p[n*8+k], k: 0-1 = W_wo rows, 2-3 = W_ri rows, 4-7 = W_sm rows
    float p[32];
#pragma unroll
    for (int k = 0; k < 8; k++) {
        const float* wbase = (k < 2) ? (W_wo + k * BLK)
                           : (k < 4) ? (W_ri + (k - 2) * BLK)
                                     : (W_sm + (k - 4) * BLK);
        float4 w = ((const float4*)wbase)[t];
#pragma unroll
        for (int n = 0; n < NS; n++)
            p[n * 8 + k] = v[n].x*w.x + v[n].y*w.y + v[n].z*w.z + v[n].w*w.w;
    }

    // Butterfly multi-value warp reduce: after this, lane L's p[0] holds warp-sum of value L
#pragma unroll
    for (int off = 16; off >= 1; off >>= 1) {
#pragma unroll
        for (int i = 0; i < 32; i++) {
            if (i < off) {
                bool hi = (lane & off) != 0;
                float send = hi ? p[i] : p[i + off];
                float recv = __shfl_xor_sync(0xffffffffu, send, off);
                float keep = hi ? p[i + off] : p[i];
                p[i] = keep + recv;
            }
        }
    }
    // ss: plain shfl reduce (4 values)
#pragma unroll
    for (int off = 16; off >= 1; off >>= 1) {
#pragma unroll
        for (int n = 0; n < NS; n++)
            ss[n] += __shfl_xor_sync(0xffffffffu, ss[n], off);
    }

    __shared__ float red[8][32];   // per-warp dot partials
    __shared__ float rss[8][4];    // per-warp sumsq
    __shared__ float s_ri[8];      // ri[n*2+m]

    red[warp][lane] = p[0];
    if (lane < 4) rss[warp][lane] = ss[lane];
    __syncthreads();

    if (t < 32) {
        const int n = t >> 3;
        const int k = t & 7;
        float dtot = 0.f, sstot = 0.f;
#pragma unroll
        for (int w = 0; w < 8; w++) { dtot += red[w][t]; sstot += rss[w][n]; }
        float rinv = rsqrtf(sstot * (1.0f / 1024.0f) + RMS_EPS);
        float val  = tanhf(dtot * rinv * INV_SCALE);
        if (k < 2) {           // write-out coefficients
            int idx = n * 2 + k;
            g_coef[(size_t)b * 24 + idx] = ds_wo[idx] * val + wo_s[idx];
        } else if (k < 4) {    // read-in coefficients (consumed below)
            int idx = n * 2 + (k - 2);
            s_ri[idx] = ds_ri[idx] * val + ri_s[idx];
        } else {               // stream mixing coefficients
            int idx = n * 4 + (k - 4);
            g_coef[(size_t)b * 24 + 8 + idx] = ds_sm[idx] * val + sm_s[idx];
        }
    }
    __syncthreads();

    float r[8];
#pragma unroll
    for (int i = 0; i < 8; i++) r[i] = s_ri[i];

    float4* xo = (float4*)(g_xread + (size_t)b * EMBED);
#pragma unroll
    for (int m = 0; m < MB; m++) {
        float4 o;
        o.x = r[0*2+m]*v[0].x + r[1*2+m]*v[1].x + r[2*2+m]*v[2].x + r[3*2+m]*v[3].x;
        o.y = r[0*2+m]*v[0].y + r[1*2+m]*v[1].y + r[2*2+m]*v[2].y + r[3*2+m]*v[3].y;
        o.z = r[0*2+m]*v[0].z + r[1*2+m]*v[1].z + r[2*2+m]*v[2].z + r[3*2+m]*v[3].z;
        o.w = r[0*2+m]*v[0].w + r[1*2+m]*v[1].w + r[2*2+m]*v[2].w + r[3*2+m]*v[3].w;
        xo[m * 256 + t] = o;
    }
}

// ---------------------------------------------------------------------------
// Kernel 2: C(16384x2048) = A(16384x2048) @ W(2048x2048)^T  in TF32 (rna)
// ---------------------------------------------------------------------------
__device__ __forceinline__ float tf32_rna(float x) {
    uint32_t u;
    asm("cvt.rna.tf32.f32 %0, %1;" : "=r"(u) : "f"(x));
    return __uint_as_float(u);
}

__device__ __forceinline__ void mma_tf32(float* d, const float* a, const float* bf) {
    asm volatile(
        "mma.sync.aligned.m16n8k8.row.col.f32.tf32.tf32.f32 "
        "{%0,%1,%2,%3}, {%4,%5,%6,%7}, {%8,%9}, {%0,%1,%2,%3};\n"
        : "+f"(d[0]), "+f"(d[1]), "+f"(d[2]), "+f"(d[3])
        : "r"(__float_as_uint(a[0])), "r"(__float_as_uint(a[1])),
          "r"(__float_as_uint(a[2])), "r"(__float_as_uint(a[3])),
          "r"(__float_as_uint(bf[0])), "r"(__float_as_uint(bf[1])));
}

#define BM 128
#define BN 128
#define BK 32
#define KTILES (EMBED / BK)
#define LDPAD 36

__global__ __launch_bounds__(256) void gemm_kernel(const float* __restrict__ Wm)
{
    __shared__ float As[BM][LDPAD];
    __shared__ float Ws[BN][LDPAD];

    const int t    = threadIdx.x;
    const int lane = t & 31;
    const int warp = t >> 5;
    const int wm   = warp >> 2;         // 0..1 : 64-row slab
    const int wn   = warp & 3;          // 0..3 : 32-col slab
    const int g    = lane >> 2;
    const int tig  = lane & 3;

    const int bm = blockIdx.y;
    const int bn = blockIdx.x;

    const float* Aptr = g_xread + (size_t)(bm * BM) * EMBED;
    const float* Bptr = Wm      + (size_t)(bn * BN) * EMBED;

    const int lr = t >> 3;              // 0..31 (row within 32-row chunk)
    const int lc = (t & 7) * 4;         // 0..28 (col start)

    float acc[4][4][4];
#pragma unroll
    for (int i = 0; i < 4; i++)
#pragma unroll
        for (int j = 0; j < 4; j++)
#pragma unroll
            for (int c = 0; c < 4; c++) acc[i][j][c] = 0.0f;

    float4 pa[4], pw[4];
#pragma unroll
    for (int i = 0; i < 4; i++) {
        pa[i] = *(const float4*)(Aptr + (size_t)(lr + 32 * i) * EMBED + lc);
        pw[i] = *(const float4*)(Bptr + (size_t)(lr + 32 * i) * EMBED + lc);
    }

    for (int kt = 0; kt < KTILES; kt++) {
        // store prefetched tile with round-to-nearest TF32 conversion
#pragma unroll
        for (int i = 0; i < 4; i++) {
            int rr = lr + 32 * i;
            As[rr][lc + 0] = tf32_rna(pa[i].x);
            As[rr][lc + 1] = tf32_rna(pa[i].y);
            As[rr][lc + 2] = tf32_rna(pa[i].z);
            As[rr][lc + 3] = tf32_rna(pa[i].w);
            Ws[rr][lc + 0] = tf32_rna(pw[i].x);
            Ws[rr][lc + 1] = tf32_rna(pw[i].y);
            Ws[rr][lc + 2] = tf32_rna(pw[i].z);
            Ws[rr][lc + 3] = tf32_rna(pw[i].w);
        }
        __syncthreads();

        if (kt + 1 < KTILES) {
            const float* An = Aptr + (kt + 1) * BK;
            const float* Bn = Bptr + (kt + 1) * BK;
#pragma unroll
            for (int i = 0; i < 4; i++) {
                pa[i] = *(const float4*)(An + (size_t)(lr + 32 * i) * EMBED + lc);
                pw[i] = *(const float4*)(Bn + (size_t)(lr + 32 * i) * EMBED + lc);
            }
        }

#pragma unroll
        for (int ks = 0; ks < 4; ks++) {
            const int kb = ks * 8;
            float a[4][4];
#pragma unroll
            for (int mf = 0; mf < 4; mf++) {
                int row = wm * 64 + mf * 16;
                a[mf][0] = As[row + g    ][kb + tig    ];
                a[mf][1] = As[row + g + 8][kb + tig    ];
                a[mf][2] = As[row + g    ][kb + tig + 4];
                a[mf][3] = As[row + g + 8][kb + tig + 4];
            }
            float bf[4][2];
#pragma unroll
            for (int nf = 0; nf < 4; nf++) {
                int col = wn * 32 + nf * 8;
                bf[nf][0] = Ws[col + g][kb + tig    ];
                bf[nf][1] = Ws[col + g][kb + tig + 4];
            }
#pragma unroll
            for (int mf = 0; mf < 4; mf++)
#pragma unroll
                for (int nf = 0; nf < 4; nf++)
                    mma_tf32(acc[mf][nf], a[mf], bf[nf]);
        }
        __syncthreads();
    }

    // Epilogue: write C (fp32)
#pragma unroll
    for (int mf = 0; mf < 4; mf++) {
        int row = bm * BM + wm * 64 + mf * 16;
#pragma unroll
        for (int nf = 0; nf < 4; nf++) {
            int col = bn * BN + wn * 32 + nf * 8 + 2 * tig;
            float2 lo = make_float2(acc[mf][nf][0], acc[mf][nf][1]);
            float2 hi = make_float2(acc[mf][nf][2], acc[mf][nf][3]);
            *(float2*)(g_mod + (size_t)(row + g    ) * EMBED + col) = lo;
            *(float2*)(g_mod + (size_t)(row + g + 8) * EMBED + col) = hi;
        }
    }
}

// ---------------------------------------------------------------------------
// Kernel 3: out[n,d] = sum_m wo[n,m]*mod[m,d] + sum_j sm[n,j]*x[j,d]
// ---------------------------------------------------------------------------
__global__ __launch_bounds__(256) void epi_kernel(
    const float* __restrict__ x, float* __restrict__ out)
{
    const int b = blockIdx.x;
    const int t = threadIdx.x;

    __shared__ float c[24];
    if (t < 24) c[t] = g_coef[(size_t)b * 24 + t];
    __syncthreads();

    const float4* xb = (const float4*)(x + (size_t)b * 4096);
    const float4* mb = (const float4*)(g_mod + (size_t)b * EMBED);
    float4* ob = (float4*)(out + (size_t)b * 4096);

    float4 m0 = mb[t];
    float4 m1 = mb[256 + t];
    float4 v[NS];
#pragma unroll
    for (int n = 0; n < NS; n++) v[n] = xb[n * 256 + t];

#pragma unroll
    for (int n = 0; n < NS; n++) {
        const float w0 = c[n * 2 + 0];
        const float w1 = c[n * 2 + 1];
        const float s0 = c[8 + n * 4 + 0];
        const float s1 = c[8 + n * 4 + 1];
        const float s2 = c[8 + n * 4 + 2];
        const float s3 = c[8 + n * 4 + 3];
        float4 o;
        o.x = w0*m0.x + w1*m1.x + s0*v[0].x + s1*v[1].x + s2*v[2].x + s3*v[3].x;
        o.y = w0*m0.y + w1*m1.y + s0*v[0].y + s1*v[1].y + s2*v[2].y + s3*v[3].y;
        o.z = w0*m0.z + w1*m1.z + s0*v[0].z + s1*v[1].z + s2*v[2].z + s3*v[3].z;
        o.w = w0*m0.w + w1*m1.w + s0*v[0].w + s1*v[1].w + s2*v[2].w + s3*v[3].w;
        ob[n * 256 + t] = o;
    }
}

// ---------------------------------------------------------------------------
extern "C" void kernel_launch(void* const* d_in, const int* in_sizes, int n_in,
                              void* d_out, int out_size)
{
    (void)in_sizes; (void)n_in; (void)out_size;
    const float* x      = (const float*)d_in[0];
    const float* wo_s   = (const float*)d_in[1];
    const float* ds_wo  = (const float*)d_in[2];
    const float* W_wo   = (const float*)d_in[3];
    const float* ri_s   = (const float*)d_in[4];
    const float* ds_ri  = (const float*)d_in[5];
    const float* W_ri   = (const float*)d_in[6];
    const float* sm_s   = (const float*)d_in[7];
    const float* ds_sm  = (const float*)d_in[8];
    const float* W_sm   = (const float*)d_in[9];
    const float* W_mod  = (const float*)d_in[10];
    float* out = (float*)d_out;

    prep_kernel<<<ROWS, 256>>>(x, wo_s, ds_wo, W_wo, ri_s, ds_ri, W_ri, sm_s, ds_sm, W_sm);

    dim3 g2(EMBED / BN, ROWS / BM);
    gemm_kernel<<<g2, 256>>>(W_mod);

    epi_kernel<<<ROWS, 256>>>(x, out);
}

// round 3
// speedup vs baseline: 1.0423x; 1.0423x over previous
#include <cuda_runtime.h>
#include <math.h>
#include <stdint.h>

#define NS 4
#define MB 2
#define BLK 1024
#define EMBED 2048
#define ROWS 16384
#define RMS_EPS 1.1920928955078125e-07f
#define INV_SCALE (1.0f/32.0f)

// Scratch (device globals: allocation-free per harness rules).
// __align__(256): these are accessed through float4* — a bare float array only
// guarantees 4B alignment and a misaligned LD.E.128 traps (err715).
__device__ __align__(256) float g_xread[(size_t)ROWS * EMBED];   // (B, 2048) fp32, m-major
__device__ __align__(256) float g_mod[(size_t)ROWS * EMBED];     // (B, 2048) GEMM output
__device__ __align__(256) float g_coef[(size_t)ROWS * 24];       // per-row: wo[8], sm[16]

// ---------------------------------------------------------------------------
// Kernel 1: RMS stats + dynamic mixing coefficients + x_read
// ---------------------------------------------------------------------------
__global__ __launch_bounds__(256) void prep_kernel(
    const float* __restrict__ x,
    const float* __restrict__ wo_s, const float* __restrict__ ds_wo, const float* __restrict__ W_wo,
    const float* __restrict__ ri_s, const float* __restrict__ ds_ri, const float* __restrict__ W_ri,
    const float* __restrict__ sm_s, const float* __restrict__ ds_sm, const float* __restrict__ W_sm)
{
    const int b    = blockIdx.x;
    const int t    = threadIdx.x;
    const int lane = t & 31;
    const int warp = t >> 5;

    const float4* xb = (const float4*)(x + (size_t)b * 4096);

    // Load this thread's slice of all 4 streams (float4 per stream)
    float4 v[NS];
#pragma unroll
    for (int n = 0; n < NS; n++) v[n] = xb[n * 256 + t];

    // sum of squares per stream
    float ss[NS];
#pragma unroll
    for (int n = 0; n < NS; n++)
        ss[n] = v[n].x*v[n].x + v[n].y*v[n].y + v[n].z*v[n].z + v[n].w*v[n].w;

    // 32 dot-product partials: p[n*8+k], k: 0-1 = W_wo rows, 2-3 = W_ri rows, 4-7 = W_sm rows
    float p[32];
#pragma unroll
    for (int k = 0; k < 8; k++) {
        const float* wbase = (k < 2) ? (W_wo + k * BLK)
                           : (k < 4) ? (W_ri + (k - 2) * BLK)
                                     : (W_sm + (k - 4) * BLK);
        float4 w = ((const float4*)wbase)[t];
#pragma unroll
        for (int n = 0; n < NS; n++)
            p[n * 8 + k] = v[n].x*w.x + v[n].y*w.y + v[n].z*w.z + v[n].w*w.w;
    }

    // Butterfly multi-value warp reduce: after this, lane L's p[0] holds warp-sum of value L
#pragma unroll
    for (int off = 16; off >= 1; off >>= 1) {
#pragma unroll
        for (int i = 0; i < 32; i++) {
            if (i < off) {
                bool hi = (lane & off) != 0;
                float send = hi ? p[i] : p[i + off];
                float recv = __shfl_xor_sync(0xffffffffu, send, off);
                float keep = hi ? p[i + off] : p[i];
                p[i] = keep + recv;
            }
        }
    }
    // ss: plain shfl reduce (4 values)
#pragma unroll
    for (int off = 16; off >= 1; off >>= 1) {
#pragma unroll
        for (int n = 0; n < NS; n++)
            ss[n] += __shfl_xor_sync(0xffffffffu, ss[n], off);
    }

    __shared__ float red[8][32];   // per-warp dot partials
    __shared__ float rss[8][4];    // per-warp sumsq
    __shared__ float s_ri[8];      // ri[n*2+m]

    red[warp][lane] = p[0];
    if (lane < 4) rss[warp][lane] = ss[lane];
    __syncthreads();

    if (t < 32) {
        const int n = t >> 3;
        const int k = t & 7;
        float dtot = 0.f, sstot = 0.f;
#pragma unroll
        for (int w = 0; w < 8; w++) { dtot += red[w][t]; sstot += rss[w][n]; }
        float rinv = rsqrtf(sstot * (1.0f / 1024.0f) + RMS_EPS);
        float val  = tanhf(dtot * rinv * INV_SCALE);
        if (k < 2) {           // write-out coefficients
            int idx = n * 2 + k;
            g_coef[(size_t)b * 24 + idx] = ds_wo[idx] * val + wo_s[idx];
        } else if (k < 4) {    // read-in coefficients (consumed below)
            int idx = n * 2 + (k - 2);
            s_ri[idx] = ds_ri[idx] * val + ri_s[idx];
        } else {               // stream mixing coefficients
            int idx = n * 4 + (k - 4);
            g_coef[(size_t)b * 24 + 8 + idx] = ds_sm[idx] * val + sm_s[idx];
        }
    }
    __syncthreads();

    float r[8];
#pragma unroll
    for (int i = 0; i < 8; i++) r[i] = s_ri[i];

    float4* xo = (float4*)(g_xread + (size_t)b * EMBED);
#pragma unroll
    for (int m = 0; m < MB; m++) {
        float4 o;
        o.x = r[0*2+m]*v[0].x + r[1*2+m]*v[1].x + r[2*2+m]*v[2].x + r[3*2+m]*v[3].x;
        o.y = r[0*2+m]*v[0].y + r[1*2+m]*v[1].y + r[2*2+m]*v[2].y + r[3*2+m]*v[3].y;
        o.z = r[0*2+m]*v[0].z + r[1*2+m]*v[1].z + r[2*2+m]*v[2].z + r[3*2+m]*v[3].z;
        o.w = r[0*2+m]*v[0].w + r[1*2+m]*v[1].w + r[2*2+m]*v[2].w + r[3*2+m]*v[3].w;
        xo[m * 256 + t] = o;
    }
}

// ---------------------------------------------------------------------------
// Kernel 2: C(16384x2048) = A(16384x2048) @ W(2048x2048)^T  in TF32 (rna)
// ---------------------------------------------------------------------------
__device__ __forceinline__ float tf32_rna(float x) {
    uint32_t u;
    asm("cvt.rna.tf32.f32 %0, %1;" : "=r"(u) : "f"(x));
    return __uint_as_float(u);
}

__device__ __forceinline__ void mma_tf32(float* d, const float* a, const float* bf) {
    asm volatile(
        "mma.sync.aligned.m16n8k8.row.col.f32.tf32.tf32.f32 "
        "{%0,%1,%2,%3}, {%4,%5,%6,%7}, {%8,%9}, {%0,%1,%2,%3};\n"
        : "+f"(d[0]), "+f"(d[1]), "+f"(d[2]), "+f"(d[3])
        : "r"(__float_as_uint(a[0])), "r"(__float_as_uint(a[1])),
          "r"(__float_as_uint(a[2])), "r"(__float_as_uint(a[3])),
          "r"(__float_as_uint(bf[0])), "r"(__float_as_uint(bf[1])));
}

#define BM 128
#define BN 128
#define BK 32
#define KTILES (EMBED / BK)
#define LDPAD 36

__global__ __launch_bounds__(256) void gemm_kernel(const float* __restrict__ Wm)
{
    __shared__ float As[BM][LDPAD];
    __shared__ float Ws[BN][LDPAD];

    const int t    = threadIdx.x;
    const int lane = t & 31;
    const int warp = t >> 5;
    const int wm   = warp >> 2;         // 0..1 : 64-row slab
    const int wn   = warp & 3;          // 0..3 : 32-col slab
    const int g    = lane >> 2;
    const int tig  = lane & 3;

    const int bm = blockIdx.y;
    const int bn = blockIdx.x;

    const float* Aptr = g_xread + (size_t)(bm * BM) * EMBED;
    const float* Bptr = Wm      + (size_t)(bn * BN) * EMBED;

    const int lr = t >> 3;              // 0..31 (row within 32-row chunk)
    const int lc = (t & 7) * 4;         // 0..28 (col start)

    float acc[4][4][4];
#pragma unroll
    for (int i = 0; i < 4; i++)
#pragma unroll
        for (int j = 0; j < 4; j++)
#pragma unroll
            for (int c = 0; c < 4; c++) acc[i][j][c] = 0.0f;

    float4 pa[4], pw[4];
#pragma unroll
    for (int i = 0; i < 4; i++) {
        pa[i] = *(const float4*)(Aptr + (size_t)(lr + 32 * i) * EMBED + lc);
        pw[i] = *(const float4*)(Bptr + (size_t)(lr + 32 * i) * EMBED + lc);
    }

    for (int kt = 0; kt < KTILES; kt++) {
        // store prefetched tile with round-to-nearest TF32 conversion
#pragma unroll
        for (int i = 0; i < 4; i++) {
            int rr = lr + 32 * i;
            As[rr][lc + 0] = tf32_rna(pa[i].x);
            As[rr][lc + 1] = tf32_rna(pa[i].y);
            As[rr][lc + 2] = tf32_rna(pa[i].z);
            As[rr][lc + 3] = tf32_rna(pa[i].w);
            Ws[rr][lc + 0] = tf32_rna(pw[i].x);
            Ws[rr][lc + 1] = tf32_rna(pw[i].y);
            Ws[rr][lc + 2] = tf32_rna(pw[i].z);
            Ws[rr][lc + 3] = tf32_rna(pw[i].w);
        }
        __syncthreads();

        if (kt + 1 < KTILES) {
            const float* An = Aptr + (kt + 1) * BK;
            const float* Bn = Bptr + (kt + 1) * BK;
#pragma unroll
            for (int i = 0; i < 4; i++) {
                pa[i] = *(const float4*)(An + (size_t)(lr + 32 * i) * EMBED + lc);
                pw[i] = *(const float4*)(Bn + (size_t)(lr + 32 * i) * EMBED + lc);
            }
        }

#pragma unroll
        for (int ks = 0; ks < 4; ks++) {
            const int kb = ks * 8;
            float a[4][4];
#pragma unroll
            for (int mf = 0; mf < 4; mf++) {
                int row = wm * 64 + mf * 16;
                a[mf][0] = As[row + g    ][kb + tig    ];
                a[mf][1] = As[row + g + 8][kb + tig    ];
                a[mf][2] = As[row + g    ][kb + tig + 4];
                a[mf][3] = As[row + g + 8][kb + tig + 4];
            }
            float bf[4][2];
#pragma unroll
            for (int nf = 0; nf < 4; nf++) {
                int col = wn * 32 + nf * 8;
                bf[nf][0] = Ws[col + g][kb + tig    ];
                bf[nf][1] = Ws[col + g][kb + tig + 4];
            }
#pragma unroll
            for (int mf = 0; mf < 4; mf++)
#pragma unroll
                for (int nf = 0; nf < 4; nf++)
                    mma_tf32(acc[mf][nf], a[mf], bf[nf]);
        }
        __syncthreads();
    }

    // Epilogue: write C (fp32)
#pragma unroll
    for (int mf = 0; mf < 4; mf++) {
        int row = bm * BM + wm * 64 + mf * 16;
#pragma unroll
        for (int nf = 0; nf < 4; nf++) {
            int col = bn * BN + wn * 32 + nf * 8 + 2 * tig;
            float2 lo = make_float2(acc[mf][nf][0], acc[mf][nf][1]);
            float2 hi = make_float2(acc[mf][nf][2], acc[mf][nf][3]);
            *(float2*)(g_mod + (size_t)(row + g    ) * EMBED + col) = lo;
            *(float2*)(g_mod + (size_t)(row + g + 8) * EMBED + col) = hi;
        }
    }
}

// ---------------------------------------------------------------------------
// Kernel 3: out[n,d] = sum_m wo[n,m]*mod[m,d] + sum_j sm[n,j]*x[j,d]
// ---------------------------------------------------------------------------
__global__ __launch_bounds__(256) void epi_kernel(
    const float* __restrict__ x, float* __restrict__ out)
{
    const int b = blockIdx.x;
    const int t = threadIdx.x;

    __shared__ float c[24];
    if (t < 24) c[t] = g_coef[(size_t)b * 24 + t];
    __syncthreads();

    const float4* xb = (const float4*)(x + (size_t)b * 4096);
    const float4* mb = (const float4*)(g_mod + (size_t)b * EMBED);
    float4* ob = (float4*)(out + (size_t)b * 4096);

    float4 m0 = mb[t];
    float4 m1 = mb[256 + t];
    float4 v[NS];
#pragma unroll
    for (int n = 0; n < NS; n++) v[n] = xb[n * 256 + t];

#pragma unroll
    for (int n = 0; n < NS; n++) {
        const float w0 = c[n * 2 + 0];
        const float w1 = c[n * 2 + 1];
        const float s0 = c[8 + n * 4 + 0];
        const float s1 = c[8 + n * 4 + 1];
        const float s2 = c[8 + n * 4 + 2];
        const float s3 = c[8 + n * 4 + 3];
        float4 o;
        o.x = w0*m0.x + w1*m1.x + s0*v[0].x + s1*v[1].x + s2*v[2].x + s3*v[3].x;
        o.y = w0*m0.y + w1*m1.y + s0*v[0].y + s1*v[1].y + s2*v[2].y + s3*v[3].y;
        o.z = w0*m0.z + w1*m1.z + s0*v[0].z + s1*v[1].z + s2*v[2].z + s3*v[3].z;
        o.w = w0*m0.w + w1*m1.w + s0*v[0].w + s1*v[1].w + s2*v[2].w + s3*v[3].w;
        ob[n * 256 + t] = o;
    }
}

// ---------------------------------------------------------------------------
extern "C" void kernel_launch(void* const* d_in, const int* in_sizes, int n_in,
                              void* d_out, int out_size)
{
    (void)in_sizes; (void)n_in; (void)out_size;
    const float* x      = (const float*)d_in[0];
    const float* wo_s   = (const float*)d_in[1];
    const float* ds_wo  = (const float*)d_in[2];
    const float* W_wo   = (const float*)d_in[3];
    const float* ri_s   = (const float*)d_in[4];
    const float* ds_ri  = (const float*)d_in[5];
    const float* W_ri   = (const float*)d_in[6];
    const float* sm_s   = (const float*)d_in[7];
    const float* ds_sm  = (const float*)d_in[8];
    const float* W_sm   = (const float*)d_in[9];
    const float* W_mod  = (const float*)d_in[10];
    float* out = (float*)d_out;

    prep_kernel<<<ROWS, 256>>>(x, wo_s, ds_wo, W_wo, ri_s, ds_ri, W_ri, sm_s, ds_sm, W_sm);

    dim3 g2(EMBED / BN, ROWS / BM);
    gemm_kernel<<<g2, 256>>>(W_mod);

    epi_kernel<<<ROWS, 256>>>(x, out);
}